// round 1
// baseline (speedup 1.0000x reference)
#include <cuda_runtime.h>
#include <math.h>

#define BB 2
#define LL 1024
#define DM 768
#define NH 12
#define DKK 64
#define FFD 3072
#define PH 32
#define ROWS (BB*LL)

// ---------------- scratch (static device allocations; no cudaMalloc) ----------------
__device__ float g_Q[BB*NH*LL*DKK];
__device__ float g_K[BB*NH*LL*DKK];
__device__ float g_V[BB*NH*LL*DKK];
__device__ float g_S[(size_t)BB*NH*LL*LL];   // 25.2M floats = 100 MB
__device__ float g_O[BB*LL*DM];
__device__ float g_Xres[BB*LL*DM];
__device__ float g_X1[BB*LL*DM];
__device__ float g_H1[BB*LL*FFD];

// ---------------- generic SGEMM: C = A(MxK) @ W(KxN) + bias, with epilogues ----------
// EPI 0: plain (+bias)
// EPI 1: relu(+bias)
// EPI 2: +bias + residual R
// EPI 3: +bias, scatter to (b, h, l, d) layout (for Q/K/V)
#define BM 128
#define BN 128
#define BKT 16
#define TM 8
#define TN 8

template<int EPI>
__global__ __launch_bounds__(256) void sgemm_kernel(
    const float* __restrict__ A, const float* __restrict__ W,
    const float* __restrict__ bias, const float* __restrict__ R,
    float* __restrict__ C, int M, int N, int K)
{
    __shared__ float As[BKT][BM];
    __shared__ float Bs[BKT][BN];
    const int tid = threadIdx.x;
    const int tx = tid & 15, ty = tid >> 4;
    const float* Ap = A + (size_t)blockIdx.y * BM * K;
    const float* Wp = W + blockIdx.x * BN;
    float acc[TM][TN] = {};

    for (int kt = 0; kt < K; kt += BKT) {
        #pragma unroll
        for (int i = 0; i < 2; i++) {
            int idx = tid + i * 256;        // 512 float4 loads of A tile
            int m  = idx >> 2;              // 0..127
            int kq = (idx & 3) << 2;        // 0,4,8,12
            float4 v = *reinterpret_cast<const float4*>(Ap + (size_t)m * K + kt + kq);
            As[kq+0][m] = v.x; As[kq+1][m] = v.y; As[kq+2][m] = v.z; As[kq+3][m] = v.w;
        }
        #pragma unroll
        for (int i = 0; i < 2; i++) {
            int idx = tid + i * 256;
            int k  = idx >> 5;              // 0..15
            int nq = (idx & 31) << 2;       // 0..124
            *reinterpret_cast<float4*>(&Bs[k][nq]) =
                *reinterpret_cast<const float4*>(Wp + (size_t)(kt + k) * N + nq);
        }
        __syncthreads();
        #pragma unroll
        for (int k = 0; k < BKT; k++) {
            float a[TM], b[TN];
            *reinterpret_cast<float4*>(&a[0]) = *reinterpret_cast<const float4*>(&As[k][ty*TM]);
            *reinterpret_cast<float4*>(&a[4]) = *reinterpret_cast<const float4*>(&As[k][ty*TM+4]);
            *reinterpret_cast<float4*>(&b[0]) = *reinterpret_cast<const float4*>(&Bs[k][tx*TN]);
            *reinterpret_cast<float4*>(&b[4]) = *reinterpret_cast<const float4*>(&Bs[k][tx*TN+4]);
            #pragma unroll
            for (int i = 0; i < TM; i++)
                #pragma unroll
                for (int j = 0; j < TN; j++)
                    acc[i][j] = fmaf(a[i], b[j], acc[i][j]);
        }
        __syncthreads();
    }

    #pragma unroll
    for (int i = 0; i < TM; i++) {
        int m = blockIdx.y * BM + ty * TM + i;
        #pragma unroll
        for (int jq = 0; jq < TN; jq += 4) {
            int n = blockIdx.x * BN + tx * TN + jq;
            float4 v;
            v.x = acc[i][jq+0] + bias[n+0];
            v.y = acc[i][jq+1] + bias[n+1];
            v.z = acc[i][jq+2] + bias[n+2];
            v.w = acc[i][jq+3] + bias[n+3];
            if (EPI == 1) {
                v.x = fmaxf(v.x, 0.f); v.y = fmaxf(v.y, 0.f);
                v.z = fmaxf(v.z, 0.f); v.w = fmaxf(v.w, 0.f);
            }
            if (EPI == 2) {
                float4 r = *reinterpret_cast<const float4*>(R + (size_t)m * N + n);
                v.x += r.x; v.y += r.y; v.z += r.z; v.w += r.w;
            }
            if (EPI == 3) {
                int b_ = m / LL, l = m % LL;
                int h  = n / DKK, d = n % DKK;
                *reinterpret_cast<float4*>(C + ((size_t)(b_*NH + h) * LL + l) * DKK + d) = v;
            } else {
                *reinterpret_cast<float4*>(C + (size_t)m * N + n) = v;
            }
        }
    }
}

// ---------------- relative-position bias MLP: write bias into S (b,h,q,k) ------------
__global__ __launch_bounds__(256) void posbias_kernel(
    const float* __restrict__ sx, const float* __restrict__ sy,
    const float* __restrict__ P1, const float* __restrict__ pb1,
    const float* __restrict__ P2, const float* __restrict__ pb2,
    float* __restrict__ S)
{
    __shared__ float sP1[2*PH], sPb1[PH], sP2[PH*NH], sPb2[NH];
    __shared__ float qx[16], qy[16], kx[16], ky[16];
    const int b  = blockIdx.z;
    const int q0 = blockIdx.y * 16, k0 = blockIdx.x * 16;
    const int tid = threadIdx.x;

    if (tid < 2*PH) sP1[tid] = P1[tid];
    if (tid < PH)   sPb1[tid] = pb1[tid];
    if (tid < NH)   sPb2[tid] = pb2[tid];
    for (int i = tid; i < PH*NH; i += 256) sP2[i] = P2[i];
    if (tid < 16) {
        qx[tid] = sx[b*LL + q0 + tid];
        qy[tid] = sy[b*LL + q0 + tid];
        kx[tid] = sx[b*LL + k0 + tid];
        ky[tid] = sy[b*LL + k0 + tid];
    }
    __syncthreads();

    const int kq = tid & 15;
    const int qq = tid >> 4;
    float rx = fminf(fmaxf(qx[qq] - kx[kq], -1000.f), 1000.f) * 0.001f;
    float ry = fminf(fmaxf(qy[qq] - ky[kq], -1000.f), 1000.f) * 0.001f;

    float hbuf[PH];
    #pragma unroll
    for (int j = 0; j < PH; j++)
        hbuf[j] = fmaxf(fmaf(rx, sP1[j], fmaf(ry, sP1[PH+j], sPb1[j])), 0.f);

    const int q = q0 + qq, k = k0 + kq;
    #pragma unroll
    for (int h = 0; h < NH; h++) {
        float s = sPb2[h];
        #pragma unroll
        for (int j = 0; j < PH; j++) s = fmaf(hbuf[j], sP2[j*NH + h], s);
        S[((size_t)(b*NH + h) * LL + q) * LL + k] = s;
    }
}

// ---------------- attention: S += 0.125 * Q @ K^T (per b,h; 64x64 tiles, K=64) -------
__global__ __launch_bounds__(256) void attn_qk_kernel(
    const float* __restrict__ Q, const float* __restrict__ Km, float* __restrict__ S)
{
    __shared__ float Qs[DKK][64];
    __shared__ float Ks[DKK][64];
    const int bh = blockIdx.z;
    const int q0 = blockIdx.y * 64, k0 = blockIdx.x * 64;
    const int tid = threadIdx.x;
    const float* Qp = Q + ((size_t)bh * LL + q0) * DKK;
    const float* Kp = Km + ((size_t)bh * LL + k0) * DKK;

    #pragma unroll
    for (int i = 0; i < 4; i++) {
        int idx = tid + i * 256;        // 1024 float4 ids
        int r  = idx >> 4;              // 0..63
        int dq = (idx & 15) << 2;       // 0..60
        float4 v = *reinterpret_cast<const float4*>(Qp + (size_t)r * DKK + dq);
        Qs[dq+0][r] = v.x; Qs[dq+1][r] = v.y; Qs[dq+2][r] = v.z; Qs[dq+3][r] = v.w;
        float4 w = *reinterpret_cast<const float4*>(Kp + (size_t)r * DKK + dq);
        Ks[dq+0][r] = w.x; Ks[dq+1][r] = w.y; Ks[dq+2][r] = w.z; Ks[dq+3][r] = w.w;
    }
    __syncthreads();

    const int tx = tid & 15, ty = tid >> 4;
    float acc[4][4] = {};
    #pragma unroll
    for (int d = 0; d < DKK; d++) {
        float a[4], b[4];
        *reinterpret_cast<float4*>(a) = *reinterpret_cast<const float4*>(&Qs[d][ty*4]);
        *reinterpret_cast<float4*>(b) = *reinterpret_cast<const float4*>(&Ks[d][tx*4]);
        #pragma unroll
        for (int i = 0; i < 4; i++)
            #pragma unroll
            for (int j = 0; j < 4; j++)
                acc[i][j] = fmaf(a[i], b[j], acc[i][j]);
    }

    #pragma unroll
    for (int i = 0; i < 4; i++) {
        size_t base = ((size_t)bh * LL + q0 + ty*4 + i) * LL + k0 + tx*4;
        float4 v = *reinterpret_cast<const float4*>(S + base);
        v.x = fmaf(acc[i][0], 0.125f, v.x);
        v.y = fmaf(acc[i][1], 0.125f, v.y);
        v.z = fmaf(acc[i][2], 0.125f, v.z);
        v.w = fmaf(acc[i][3], 0.125f, v.w);
        *reinterpret_cast<float4*>(S + base) = v;
    }
}

// ---------------- softmax over last dim of S (rows of length 1024) -------------------
__global__ __launch_bounds__(256) void softmax_kernel(float* __restrict__ S)
{
    __shared__ float red[256];
    const size_t row = blockIdx.x;
    float* p = S + row * LL;
    const int tid = threadIdx.x;
    float v[4];
    #pragma unroll
    for (int i = 0; i < 4; i++) v[i] = p[tid + i*256];
    float m = fmaxf(fmaxf(v[0], v[1]), fmaxf(v[2], v[3]));
    red[tid] = m; __syncthreads();
    for (int s = 128; s > 0; s >>= 1) { if (tid < s) red[tid] = fmaxf(red[tid], red[tid+s]); __syncthreads(); }
    m = red[0]; __syncthreads();
    float sum = 0.f;
    #pragma unroll
    for (int i = 0; i < 4; i++) { v[i] = __expf(v[i] - m); sum += v[i]; }
    red[tid] = sum; __syncthreads();
    for (int s = 128; s > 0; s >>= 1) { if (tid < s) red[tid] += red[tid+s]; __syncthreads(); }
    float inv = 1.f / red[0];
    #pragma unroll
    for (int i = 0; i < 4; i++) p[tid + i*256] = v[i] * inv;
}

// ---------------- attention: O(b,l,h*64+d) = softmax(S) @ V --------------------------
__global__ __launch_bounds__(256) void attn_av_kernel(
    const float* __restrict__ S, const float* __restrict__ V, float* __restrict__ O)
{
    __shared__ float Ss[32][64];
    __shared__ float Vs[32][64];
    const int bh = blockIdx.z, b = bh / NH, h = bh % NH;
    const int q0 = blockIdx.y * 64;
    const int tid = threadIdx.x;
    const int tx = tid & 15, ty = tid >> 4;
    float acc[4][4] = {};
    const float* Sp = S + ((size_t)bh * LL + q0) * LL;
    const float* Vp = V + (size_t)bh * LL * DKK;

    for (int kt = 0; kt < LL; kt += 32) {
        #pragma unroll
        for (int i = 0; i < 2; i++) {
            int idx = tid + i * 256;     // 512 float4 ids
            int q  = idx >> 3;           // 0..63
            int kq = (idx & 7) << 2;     // 0..28
            float4 v = *reinterpret_cast<const float4*>(Sp + (size_t)q * LL + kt + kq);
            Ss[kq+0][q] = v.x; Ss[kq+1][q] = v.y; Ss[kq+2][q] = v.z; Ss[kq+3][q] = v.w;
            int k  = idx >> 4;           // 0..31
            int dq = (idx & 15) << 2;    // 0..60
            *reinterpret_cast<float4*>(&Vs[k][dq]) =
                *reinterpret_cast<const float4*>(Vp + (size_t)(kt + k) * DKK + dq);
        }
        __syncthreads();
        #pragma unroll
        for (int kk = 0; kk < 32; kk++) {
            float a[4], bb[4];
            *reinterpret_cast<float4*>(a)  = *reinterpret_cast<const float4*>(&Ss[kk][ty*4]);
            *reinterpret_cast<float4*>(bb) = *reinterpret_cast<const float4*>(&Vs[kk][tx*4]);
            #pragma unroll
            for (int i = 0; i < 4; i++)
                #pragma unroll
                for (int j = 0; j < 4; j++)
                    acc[i][j] = fmaf(a[i], bb[j], acc[i][j]);
        }
        __syncthreads();
    }

    #pragma unroll
    for (int i = 0; i < 4; i++) {
        int q = q0 + ty*4 + i;
        float4 v = make_float4(acc[i][0], acc[i][1], acc[i][2], acc[i][3]);
        *reinterpret_cast<float4*>(O + ((size_t)b * LL + q) * DM + h * DKK + tx*4) = v;
    }
}

// ---------------- layernorm over last dim (768) --------------------------------------
__global__ __launch_bounds__(256) void layernorm_kernel(
    const float* __restrict__ X, const float* __restrict__ g, const float* __restrict__ be,
    float* __restrict__ Y)
{
    __shared__ float red[256];
    const size_t row = blockIdx.x;
    const float* p = X + row * DM;
    float* o = Y + row * DM;
    const int tid = threadIdx.x;
    float v[3];
    float s = 0.f;
    #pragma unroll
    for (int i = 0; i < 3; i++) { v[i] = p[tid + i*256]; s += v[i]; }
    red[tid] = s; __syncthreads();
    for (int st = 128; st > 0; st >>= 1) { if (tid < st) red[tid] += red[tid+st]; __syncthreads(); }
    float mean = red[0] * (1.f/DM); __syncthreads();
    float sq = 0.f;
    #pragma unroll
    for (int i = 0; i < 3; i++) { float d = v[i] - mean; sq += d*d; }
    red[tid] = sq; __syncthreads();
    for (int st = 128; st > 0; st >>= 1) { if (tid < st) red[tid] += red[tid+st]; __syncthreads(); }
    float rstd = rsqrtf(red[0] * (1.f/DM) + 1e-5f);
    #pragma unroll
    for (int i = 0; i < 3; i++) {
        int c = tid + i*256;
        o[c] = (v[i] - mean) * rstd * g[c] + be[c];
    }
}

// ---------------- launch ------------------------------------------------------------
extern "C" void kernel_launch(void* const* d_in, const int* in_sizes, int n_in,
                              void* d_out, int out_size)
{
    const float* src = (const float*)d_in[0];
    const float* sx  = (const float*)d_in[1];
    const float* sy  = (const float*)d_in[2];
    const float* Wq  = (const float*)d_in[3];  const float* bq  = (const float*)d_in[4];
    const float* Wk  = (const float*)d_in[5];  const float* bk  = (const float*)d_in[6];
    const float* Wv  = (const float*)d_in[7];  const float* bv  = (const float*)d_in[8];
    const float* Wo  = (const float*)d_in[9];  const float* bo  = (const float*)d_in[10];
    const float* P1  = (const float*)d_in[11]; const float* pb1 = (const float*)d_in[12];
    const float* P2  = (const float*)d_in[13]; const float* pb2 = (const float*)d_in[14];
    const float* W1  = (const float*)d_in[15]; const float* b1  = (const float*)d_in[16];
    const float* W2  = (const float*)d_in[17]; const float* b2  = (const float*)d_in[18];
    const float* g1  = (const float*)d_in[19]; const float* be1 = (const float*)d_in[20];
    const float* g2  = (const float*)d_in[21]; const float* be2 = (const float*)d_in[22];
    float* out = (float*)d_out;

    float *Q, *K, *V, *S, *O, *Xres, *X1, *H1;
    cudaGetSymbolAddress((void**)&Q,    g_Q);
    cudaGetSymbolAddress((void**)&K,    g_K);
    cudaGetSymbolAddress((void**)&V,    g_V);
    cudaGetSymbolAddress((void**)&S,    g_S);
    cudaGetSymbolAddress((void**)&O,    g_O);
    cudaGetSymbolAddress((void**)&Xres, g_Xres);
    cudaGetSymbolAddress((void**)&X1,   g_X1);
    cudaGetSymbolAddress((void**)&H1,   g_H1);

    // 1) relative-position bias -> S
    posbias_kernel<<<dim3(LL/16, LL/16, BB), 256>>>(sx, sy, P1, pb1, P2, pb2, S);

    // 2) Q,K,V projections (scatter to (b,h,l,d))
    dim3 gProj(DM/BN, ROWS/BM);
    sgemm_kernel<3><<<gProj, 256>>>(src, Wq, bq, nullptr, Q, ROWS, DM, DM);
    sgemm_kernel<3><<<gProj, 256>>>(src, Wk, bk, nullptr, K, ROWS, DM, DM);
    sgemm_kernel<3><<<gProj, 256>>>(src, Wv, bv, nullptr, V, ROWS, DM, DM);

    // 3) S += Q K^T / 8
    attn_qk_kernel<<<dim3(LL/64, LL/64, BB*NH), 256>>>(Q, K, S);

    // 4) softmax rows
    softmax_kernel<<<BB*NH*LL, 256>>>(S);

    // 5) O = P @ V  -> (b, l, h*64+d)
    attn_av_kernel<<<dim3(1, LL/64, BB*NH), 256>>>(S, V, O);

    // 6) Xres = src + O @ Wo + bo ; LN1 -> X1
    sgemm_kernel<2><<<dim3(DM/BN, ROWS/BM), 256>>>(O, Wo, bo, src, Xres, ROWS, DM, DM);
    layernorm_kernel<<<ROWS, 256>>>(Xres, g1, be1, X1);

    // 7) FFN
    sgemm_kernel<1><<<dim3(FFD/BN, ROWS/BM), 256>>>(X1, W1, b1, nullptr, H1, ROWS, FFD, DM);
    sgemm_kernel<2><<<dim3(DM/BN, ROWS/BM), 256>>>(H1, W2, b2, X1, Xres, ROWS, DM, FFD);

    // 8) LN2 -> output
    layernorm_kernel<<<ROWS, 256>>>(Xres, g2, be2, out);
}

// round 2
// speedup vs baseline: 2.0264x; 2.0264x over previous
#include <cuda_runtime.h>
#include <math.h>

#define BB 2
#define LL 1024
#define DM 768
#define NH 12
#define DKK 64
#define FFD 3072
#define PH 32
#define ROWS (BB*LL)

// ---------------- scratch ----------------
__device__ float g_Q[BB*NH*LL*DKK];
__device__ float g_K[BB*NH*LL*DKK];
__device__ float g_V[BB*NH*LL*DKK];
__device__ float g_S[(size_t)BB*NH*LL*LL];
__device__ float g_O[BB*LL*DM];
__device__ float g_Xres[BB*LL*DM];
__device__ float g_X1[BB*LL*DM];
__device__ float g_H1[BB*LL*FFD];

// ---------------- tf32 helpers ----------------
__device__ __forceinline__ float tf32f(float x) {
    unsigned u;
    asm("cvt.rna.tf32.f32 %0, %1;" : "=r"(u) : "f"(x));
    return __uint_as_float(u);
}

__device__ __forceinline__ void mma_tf32(float* c, const unsigned* a, const unsigned* b) {
    asm volatile(
        "mma.sync.aligned.m16n8k8.row.col.f32.tf32.tf32.f32 "
        "{%0,%1,%2,%3}, {%4,%5,%6,%7}, {%8,%9}, {%0,%1,%2,%3};"
        : "+f"(c[0]), "+f"(c[1]), "+f"(c[2]), "+f"(c[3])
        : "r"(a[0]), "r"(a[1]), "r"(a[2]), "r"(a[3]), "r"(b[0]), "r"(b[1]));
}

// ---------------- tensor-core GEMM ----------------
// C[z] = epi( A[z](M x K) @ op(B[z])(K x N) )
// BT: B stored as [N, K] row-major (so op(B) = B^T; native for mma row.col)
// EPI 0: +bias       1: relu(+bias)        2: +bias +R residual
//     3: QKV fused scatter (B/B1/B2 select by blockIdx.x, out (b,h,l,d))
//     4: alpha*acc + C (read-modify-write; used for QK^T into S)
//     5: plain store, C offset = (z/NH)*LL*DM + (z%NH)*DKK (AV output)
// Block: 128 x BN, K-tile 16, 256 threads, 8 warps (2 x BN/WN), warp tile 64 x WN.
template<int EPI, bool BT, int BN, int WN>
__global__ __launch_bounds__(256, 2) void tgemm(
    const float* __restrict__ A, int lda, long sAz,
    const float* __restrict__ B, int ldb, long sBz,
    const float* __restrict__ bias,
    const float* __restrict__ Rres,
    float* __restrict__ C, int ldc, long sCz,
    int K, float alpha,
    const float* __restrict__ B1, const float* __restrict__ B2,
    const float* __restrict__ bias1, const float* __restrict__ bias2,
    float* __restrict__ C1, float* __restrict__ C2)
{
    constexpr int NT = WN / 8;       // n-tiles per warp
    constexpr int AS2 = 132;         // float2 stride (>=128, ==4 mod 16 -> conflict-free)
    constexpr int BS2 = BN + 4;      // 132 or 68, both ==4 mod 16
    __shared__ float As[16 * AS2 * 2];
    __shared__ float Bs[16 * BS2 * 2];

    const int tid = threadIdx.x;
    const int lane = tid & 31, w = tid >> 5;
    const int wm = w & 1, wn = w >> 1;
    const int g = lane >> 2, t4 = lane & 3;
    const int bz = blockIdx.z;
    int bx = blockIdx.x;
    const int m0 = blockIdx.y * 128;

    const float* Ap = A + (size_t)bz * sAz;
    const float* Bp; const float* biasp = bias; float* Cp;
    if (EPI == 3) {
        int sel = bx / 6; bx -= sel * 6;
        Bp    = sel == 0 ? B    : (sel == 1 ? B1    : B2);
        biasp = sel == 0 ? bias : (sel == 1 ? bias1 : bias2);
        Cp    = sel == 0 ? C    : (sel == 1 ? C1    : C2);
    } else {
        Bp = B + (size_t)bz * sBz;
        if (EPI == 5) Cp = C + (size_t)(bz / NH) * (LL * DM) + (size_t)(bz % NH) * DKK;
        else          Cp = C + (size_t)bz * sCz;
    }
    const int n0 = bx * BN;

    float acc[4][NT][4];
    #pragma unroll
    for (int i = 0; i < 4; i++)
        #pragma unroll
        for (int j = 0; j < NT; j++)
            #pragma unroll
            for (int q = 0; q < 4; q++) acc[i][j][q] = 0.f;

    const int am  = tid >> 2;          // 0..63
    const int akq = (tid & 3) << 2;    // 0,4,8,12
    float4 av[2], bv[2];

    auto ldgA = [&](int kt) {
        av[0] = *(const float4*)(Ap + (size_t)(m0 + am)      * lda + kt + akq);
        av[1] = *(const float4*)(Ap + (size_t)(m0 + am + 64) * lda + kt + akq);
    };
    auto ldgB = [&](int kt) {
        if (BT) {
            bv[0] = *(const float4*)(Bp + (size_t)(n0 + am)      * ldb + kt + akq);
            bv[1] = *(const float4*)(Bp + (size_t)(n0 + am + 64) * ldb + kt + akq);
        } else if (BN == 128) {
            int krow = tid >> 5, n4 = (tid & 31) << 2;
            bv[0] = *(const float4*)(Bp + (size_t)(kt + krow)     * ldb + n0 + n4);
            bv[1] = *(const float4*)(Bp + (size_t)(kt + krow + 8) * ldb + n0 + n4);
        } else {
            int krow = tid >> 4, n4 = (tid & 15) << 2;
            bv[0] = *(const float4*)(Bp + (size_t)(kt + krow) * ldb + n0 + n4);
        }
    };
    auto stsA = [&]() {
        // float4 covers k = akq..akq+3 -> kk = akq>>3, h = (akq>>2)&1, c = 0..3
        int kk = akq >> 3, h = (akq >> 2) & 1;
        float* p = As + ((size_t)(kk * 4) * AS2 + am) * 2 + h;
        p[0]         = tf32f(av[0].x);
        p[AS2 * 2]   = tf32f(av[0].y);
        p[AS2 * 4]   = tf32f(av[0].z);
        p[AS2 * 6]   = tf32f(av[0].w);
        float* p1 = p + 128;
        p1[0]        = tf32f(av[1].x);
        p1[AS2 * 2]  = tf32f(av[1].y);
        p1[AS2 * 4]  = tf32f(av[1].z);
        p1[AS2 * 6]  = tf32f(av[1].w);
    };
    auto stsB = [&]() {
        if (BT) {
            int kk = akq >> 3, h = (akq >> 2) & 1;
            float* p = Bs + ((size_t)(kk * 4) * BS2 + am) * 2 + h;
            p[0]        = tf32f(bv[0].x);
            p[BS2 * 2]  = tf32f(bv[0].y);
            p[BS2 * 4]  = tf32f(bv[0].z);
            p[BS2 * 6]  = tf32f(bv[0].w);
            float* p1 = p + 128;
            p1[0]       = tf32f(bv[1].x);
            p1[BS2 * 2] = tf32f(bv[1].y);
            p1[BS2 * 4] = tf32f(bv[1].z);
            p1[BS2 * 6] = tf32f(bv[1].w);
        } else if (BN == 128) {
            int krow = tid >> 5, n4 = (tid & 31) << 2;
            {
                int kk = krow >> 3, c = krow & 3, h = (krow >> 2) & 1;
                float* p = Bs + ((size_t)(kk * 4 + c) * BS2 + n4) * 2 + h;
                p[0] = tf32f(bv[0].x); p[2] = tf32f(bv[0].y);
                p[4] = tf32f(bv[0].z); p[6] = tf32f(bv[0].w);
            }
            {
                int kr2 = krow + 8;
                int kk = kr2 >> 3, c = kr2 & 3, h = (kr2 >> 2) & 1;
                float* p = Bs + ((size_t)(kk * 4 + c) * BS2 + n4) * 2 + h;
                p[0] = tf32f(bv[1].x); p[2] = tf32f(bv[1].y);
                p[4] = tf32f(bv[1].z); p[6] = tf32f(bv[1].w);
            }
        } else {
            int krow = tid >> 4, n4 = (tid & 15) << 2;
            int kk = krow >> 3, c = krow & 3, h = (krow >> 2) & 1;
            float* p = Bs + ((size_t)(kk * 4 + c) * BS2 + n4) * 2 + h;
            p[0] = tf32f(bv[0].x); p[2] = tf32f(bv[0].y);
            p[4] = tf32f(bv[0].z); p[6] = tf32f(bv[0].w);
        }
    };
    auto compute = [&]() {
        #pragma unroll
        for (int kk = 0; kk < 2; kk++) {
            unsigned aF[4][4];
            #pragma unroll
            for (int i = 0; i < 4; i++) {
                int mb = wm * 64 + i * 16 + g;
                float2 lo = *(const float2*)(As + ((kk * 4 + t4) * AS2 + mb) * 2);
                float2 hi = *(const float2*)(As + ((kk * 4 + t4) * AS2 + mb + 8) * 2);
                aF[i][0] = __float_as_uint(lo.x);
                aF[i][1] = __float_as_uint(hi.x);
                aF[i][2] = __float_as_uint(lo.y);
                aF[i][3] = __float_as_uint(hi.y);
            }
            unsigned bF[NT][2];
            #pragma unroll
            for (int j = 0; j < NT; j++) {
                float2 bb = *(const float2*)(Bs + ((kk * 4 + t4) * BS2 + wn * WN + j * 8 + g) * 2);
                bF[j][0] = __float_as_uint(bb.x);
                bF[j][1] = __float_as_uint(bb.y);
            }
            #pragma unroll
            for (int i = 0; i < 4; i++)
                #pragma unroll
                for (int j = 0; j < NT; j++)
                    mma_tf32(acc[i][j], aF[i], bF[j]);
        }
    };

    ldgA(0); ldgB(0);
    stsA(); stsB();
    __syncthreads();
    for (int kt = 16;; kt += 16) {
        bool more = kt < K;
        if (more) { ldgA(kt); ldgB(kt); }
        compute();
        if (!more) break;
        __syncthreads();
        stsA(); stsB();
        __syncthreads();
    }

    // epilogue
    auto epi = [&](int row, int col, float2 v) {
        if (EPI == 4) {
            float2 old = *(const float2*)(Cp + (size_t)row * ldc + col);
            v.x = fmaf(v.x, alpha, old.x);
            v.y = fmaf(v.y, alpha, old.y);
            *(float2*)(Cp + (size_t)row * ldc + col) = v;
            return;
        }
        if (EPI == 5) {
            *(float2*)(Cp + (size_t)row * ldc + col) = v;
            return;
        }
        float2 bb = *(const float2*)(biasp + col);
        v.x += bb.x; v.y += bb.y;
        if (EPI == 1) { v.x = fmaxf(v.x, 0.f); v.y = fmaxf(v.y, 0.f); }
        if (EPI == 2) {
            float2 r = *(const float2*)(Rres + (size_t)row * ldc + col);
            v.x += r.x; v.y += r.y;
        }
        if (EPI == 3) {
            int h = col >> 6, d = col & 63;
            float* dst = Cp + ((((size_t)(row >> 10) * NH + h) * LL + (row & 1023)) * DKK + d);
            *(float2*)dst = v;
            return;
        }
        *(float2*)(Cp + (size_t)row * ldc + col) = v;
    };

    #pragma unroll
    for (int i = 0; i < 4; i++) {
        int r0 = m0 + wm * 64 + i * 16 + g;
        #pragma unroll
        for (int j = 0; j < NT; j++) {
            int col = n0 + wn * WN + j * 8 + t4 * 2;
            epi(r0,     col, make_float2(acc[i][j][0], acc[i][j][1]));
            epi(r0 + 8, col, make_float2(acc[i][j][2], acc[i][j][3]));
        }
    }
}

// ---------------- relative-position bias MLP -> S (b,h,q,k) ----------------
__global__ __launch_bounds__(256) void posbias_kernel(
    const float* __restrict__ sx, const float* __restrict__ sy,
    const float* __restrict__ P1, const float* __restrict__ pb1,
    const float* __restrict__ P2, const float* __restrict__ pb2,
    float* __restrict__ S)
{
    __shared__ float sP1[2*PH], sPb1[PH], sP2[PH*NH], sPb2[NH];
    __shared__ float qx[16], qy[16], kx[16], ky[16];
    const int b  = blockIdx.z;
    const int q0 = blockIdx.y * 16, k0 = blockIdx.x * 16;
    const int tid = threadIdx.x;

    if (tid < 2*PH) sP1[tid] = P1[tid];
    if (tid < PH)   sPb1[tid] = pb1[tid];
    if (tid < NH)   sPb2[tid] = pb2[tid];
    for (int i = tid; i < PH*NH; i += 256) sP2[i] = P2[i];
    if (tid < 16) {
        qx[tid] = sx[b*LL + q0 + tid];
        qy[tid] = sy[b*LL + q0 + tid];
        kx[tid] = sx[b*LL + k0 + tid];
        ky[tid] = sy[b*LL + k0 + tid];
    }
    __syncthreads();

    const int kq = tid & 15;
    const int qq = tid >> 4;
    float rx = fminf(fmaxf(qx[qq] - kx[kq], -1000.f), 1000.f) * 0.001f;
    float ry = fminf(fmaxf(qy[qq] - ky[kq], -1000.f), 1000.f) * 0.001f;

    float hbuf[PH];
    #pragma unroll
    for (int j = 0; j < PH; j++)
        hbuf[j] = fmaxf(fmaf(rx, sP1[j], fmaf(ry, sP1[PH+j], sPb1[j])), 0.f);

    const int q = q0 + qq, k = k0 + kq;
    #pragma unroll
    for (int h = 0; h < NH; h++) {
        float s = sPb2[h];
        #pragma unroll
        for (int j = 0; j < PH; j++) s = fmaf(hbuf[j], sP2[j*NH + h], s);
        S[((size_t)(b*NH + h) * LL + q) * LL + k] = s;
    }
}

// ---------------- softmax over rows of length 1024 ----------------
__global__ __launch_bounds__(256) void softmax_kernel(float* __restrict__ S)
{
    __shared__ float red[256];
    const size_t row = blockIdx.x;
    float* p = S + row * LL;
    const int tid = threadIdx.x;
    float v[4];
    #pragma unroll
    for (int i = 0; i < 4; i++) v[i] = p[tid + i*256];
    float m = fmaxf(fmaxf(v[0], v[1]), fmaxf(v[2], v[3]));
    red[tid] = m; __syncthreads();
    for (int s = 128; s > 0; s >>= 1) { if (tid < s) red[tid] = fmaxf(red[tid], red[tid+s]); __syncthreads(); }
    m = red[0]; __syncthreads();
    float sum = 0.f;
    #pragma unroll
    for (int i = 0; i < 4; i++) { v[i] = __expf(v[i] - m); sum += v[i]; }
    red[tid] = sum; __syncthreads();
    for (int s = 128; s > 0; s >>= 1) { if (tid < s) red[tid] += red[tid+s]; __syncthreads(); }
    float inv = 1.f / red[0];
    #pragma unroll
    for (int i = 0; i < 4; i++) p[tid + i*256] = v[i] * inv;
}

// ---------------- layernorm over last dim (768) ----------------
__global__ __launch_bounds__(256) void layernorm_kernel(
    const float* __restrict__ X, const float* __restrict__ g, const float* __restrict__ be,
    float* __restrict__ Y)
{
    __shared__ float red[256];
    const size_t row = blockIdx.x;
    const float* p = X + row * DM;
    float* o = Y + row * DM;
    const int tid = threadIdx.x;
    float v[3];
    float s = 0.f;
    #pragma unroll
    for (int i = 0; i < 3; i++) { v[i] = p[tid + i*256]; s += v[i]; }
    red[tid] = s; __syncthreads();
    for (int st = 128; st > 0; st >>= 1) { if (tid < st) red[tid] += red[tid+st]; __syncthreads(); }
    float mean = red[0] * (1.f/DM); __syncthreads();
    float sq = 0.f;
    #pragma unroll
    for (int i = 0; i < 3; i++) { float d = v[i] - mean; sq += d*d; }
    red[tid] = sq; __syncthreads();
    for (int st = 128; st > 0; st >>= 1) { if (tid < st) red[tid] += red[tid+st]; __syncthreads(); }
    float rstd = rsqrtf(red[0] * (1.f/DM) + 1e-5f);
    #pragma unroll
    for (int i = 0; i < 3; i++) {
        int c = tid + i*256;
        o[c] = (v[i] - mean) * rstd * g[c] + be[c];
    }
}

// ---------------- launch ----------------
extern "C" void kernel_launch(void* const* d_in, const int* in_sizes, int n_in,
                              void* d_out, int out_size)
{
    const float* src = (const float*)d_in[0];
    const float* sx  = (const float*)d_in[1];
    const float* sy  = (const float*)d_in[2];
    const float* Wq  = (const float*)d_in[3];  const float* bq  = (const float*)d_in[4];
    const float* Wk  = (const float*)d_in[5];  const float* bk  = (const float*)d_in[6];
    const float* Wv  = (const float*)d_in[7];  const float* bv  = (const float*)d_in[8];
    const float* Wo  = (const float*)d_in[9];  const float* bo  = (const float*)d_in[10];
    const float* P1  = (const float*)d_in[11]; const float* pb1 = (const float*)d_in[12];
    const float* P2  = (const float*)d_in[13]; const float* pb2 = (const float*)d_in[14];
    const float* W1  = (const float*)d_in[15]; const float* b1  = (const float*)d_in[16];
    const float* W2  = (const float*)d_in[17]; const float* b2  = (const float*)d_in[18];
    const float* g1  = (const float*)d_in[19]; const float* be1 = (const float*)d_in[20];
    const float* g2  = (const float*)d_in[21]; const float* be2 = (const float*)d_in[22];
    float* out = (float*)d_out;

    float *Q, *K, *V, *S, *O, *Xres, *X1, *H1;
    cudaGetSymbolAddress((void**)&Q,    g_Q);
    cudaGetSymbolAddress((void**)&K,    g_K);
    cudaGetSymbolAddress((void**)&V,    g_V);
    cudaGetSymbolAddress((void**)&S,    g_S);
    cudaGetSymbolAddress((void**)&O,    g_O);
    cudaGetSymbolAddress((void**)&Xres, g_Xres);
    cudaGetSymbolAddress((void**)&X1,   g_X1);
    cudaGetSymbolAddress((void**)&H1,   g_H1);

    // 1) relative-position bias -> S
    posbias_kernel<<<dim3(LL/16, LL/16, BB), 256>>>(sx, sy, P1, pb1, P2, pb2, S);

    // 2) fused QKV projections (tf32 MMA), scatter to (b,h,l,d)
    tgemm<3, false, 128, 32><<<dim3(18, ROWS/128, 1), 256>>>(
        src, DM, 0, Wq, DM, 0, bq, nullptr, Q, 0, 0, DM, 1.f,
        Wk, Wv, bk, bv, K, V);

    // 3) S = 0.125 * Q K^T + S(bias)   (batched over b*h)
    tgemm<4, true, 128, 32><<<dim3(LL/128, LL/128, BB*NH), 256>>>(
        Q, DKK, (long)LL*DKK, K, DKK, (long)LL*DKK, nullptr, nullptr,
        S, LL, (long)LL*LL, DKK, 0.125f,
        nullptr, nullptr, nullptr, nullptr, nullptr, nullptr);

    // 4) softmax rows
    softmax_kernel<<<BB*NH*LL, 256>>>(S);

    // 5) O = P @ V  -> (b, l, h*64+d)
    tgemm<5, false, 64, 16><<<dim3(1, LL/128, BB*NH), 256>>>(
        S, LL, (long)LL*LL, V, DKK, (long)LL*DKK, nullptr, nullptr,
        O, DM, 0, LL, 1.f,
        nullptr, nullptr, nullptr, nullptr, nullptr, nullptr);

    // 6) Xres = src + O @ Wo + bo ; LN1 -> X1
    tgemm<2, false, 64, 16><<<dim3(DM/64, ROWS/128, 1), 256>>>(
        O, DM, 0, Wo, DM, 0, bo, src, Xres, DM, 0, DM, 1.f,
        nullptr, nullptr, nullptr, nullptr, nullptr, nullptr);
    layernorm_kernel<<<ROWS, 256>>>(Xres, g1, be1, X1);

    // 7) FFN
    tgemm<1, false, 128, 32><<<dim3(FFD/128, ROWS/128, 1), 256>>>(
        X1, DM, 0, W1, FFD, 0, b1, nullptr, H1, FFD, 0, DM, 1.f,
        nullptr, nullptr, nullptr, nullptr, nullptr, nullptr);
    tgemm<2, false, 64, 16><<<dim3(DM/64, ROWS/128, 1), 256>>>(
        H1, FFD, 0, W2, DM, 0, b2, X1, Xres, DM, 0, FFD, 1.f,
        nullptr, nullptr, nullptr, nullptr, nullptr, nullptr);

    // 8) LN2 -> output
    layernorm_kernel<<<ROWS, 256>>>(Xres, g2, be2, out);
}

// round 3
// speedup vs baseline: 2.6433x; 1.3044x over previous
#include <cuda_runtime.h>
#include <math.h>

#define BB 2
#define LL 1024
#define DM 768
#define NH 12
#define DKK 64
#define FFD 3072
#define PH 32
#define ROWS (BB*LL)

// ---------------- scratch ----------------
__device__ float g_Q[BB*NH*LL*DKK];
__device__ float g_K[BB*NH*LL*DKK];
__device__ float g_V[BB*NH*LL*DKK];
__device__ float g_S[(size_t)BB*NH*LL*LL];
__device__ float g_O[BB*LL*DM];
__device__ float g_Xres[BB*LL*DM];
__device__ float g_X1[BB*LL*DM];
__device__ float g_H1[BB*LL*FFD];

// ---------------- helpers ----------------
__device__ __forceinline__ unsigned tf32u(float x) {
    unsigned u;
    asm("cvt.rna.tf32.f32 %0, %1;" : "=r"(u) : "f"(x));
    return u;
}

__device__ __forceinline__ void mma_tf32(float* c, const unsigned* a, const unsigned* b) {
    asm volatile(
        "mma.sync.aligned.m16n8k8.row.col.f32.tf32.tf32.f32 "
        "{%0,%1,%2,%3}, {%4,%5,%6,%7}, {%8,%9}, {%0,%1,%2,%3};"
        : "+f"(c[0]), "+f"(c[1]), "+f"(c[2]), "+f"(c[3])
        : "r"(a[0]), "r"(a[1]), "r"(a[2]), "r"(a[3]), "r"(b[0]), "r"(b[1]));
}

__device__ __forceinline__ void cp16(float* dst_smem, const float* src) {
    unsigned d = (unsigned)__cvta_generic_to_shared(dst_smem);
    asm volatile("cp.async.cg.shared.global [%0], [%1], 16;" :: "r"(d), "l"(src));
}
__device__ __forceinline__ void cp_commit() { asm volatile("cp.async.commit_group;"); }
template<int N> __device__ __forceinline__ void cp_wait() {
    asm volatile("cp.async.wait_group %0;" :: "n"(N));
}

// ---------------- tensor-core GEMM (cp.async 2-stage pipeline) ----------------
// C[z] = epi( A[z](M x K) @ op(B[z])(K x N) )
// BT: B stored [N, K] row-major (op(B)=B^T, native for mma row.col)
// EPI 0: +bias  1: relu(+bias)  2: +bias +R residual
//     3: fused QKV scatter (B/B1/B2 by blockIdx.x, out (b,h,l,d))
//     4: alpha*acc + C (RMW; QK^T into S which holds the bias)
template<int EPI, bool BT, int BN, int WN>
__global__ __launch_bounds__(256, 2) void tgemm(
    const float* __restrict__ A, int lda, long sAz,
    const float* __restrict__ B, int ldb, long sBz,
    const float* __restrict__ bias,
    const float* __restrict__ Rres,
    float* __restrict__ C, int ldc, long sCz,
    int K, float alpha,
    const float* __restrict__ B1, const float* __restrict__ B2,
    const float* __restrict__ bias1, const float* __restrict__ bias2,
    float* __restrict__ C1, float* __restrict__ C2)
{
    constexpr int NT = WN / 8;
    constexpr int AP = 20;                 // A row stride (16 k + 4 pad)
    constexpr int BP = BN + 4;             // Bs row stride (k-major case)
    constexpr int ASZ = 128 * AP;
    constexpr int BSZ = BT ? BN * AP : 16 * BP;
    __shared__ float As[2 * ASZ];
    __shared__ float Bs[2 * BSZ];

    const int tid = threadIdx.x;
    const int lane = tid & 31, w = tid >> 5;
    const int wm = w & 1, wn = w >> 1;
    const int g = lane >> 2, t4 = lane & 3;
    const int bz = blockIdx.z;
    int bx = blockIdx.x;
    const int m0 = blockIdx.y * 128;

    const float* Ap = A + (size_t)bz * sAz;
    const float* Bp; const float* biasp = bias; float* Cp;
    if (EPI == 3) {
        int sel = bx / 6; bx -= sel * 6;
        Bp    = sel == 0 ? B    : (sel == 1 ? B1    : B2);
        biasp = sel == 0 ? bias : (sel == 1 ? bias1 : bias2);
        Cp    = sel == 0 ? C    : (sel == 1 ? C1    : C2);
    } else {
        Bp = B + (size_t)bz * sBz;
        Cp = C + (size_t)bz * sCz;
    }
    const int n0 = bx * BN;

    float acc[4][NT][4];
    #pragma unroll
    for (int i = 0; i < 4; i++)
        #pragma unroll
        for (int j = 0; j < NT; j++)
            #pragma unroll
            for (int q = 0; q < 4; q++) acc[i][j][q] = 0.f;

    auto loadA = [&](int kt, int st) {
        #pragma unroll
        for (int i = 0; i < 2; i++) {
            int idx = tid + i * 256;
            int m = idx >> 2, k4 = (idx & 3) << 2;
            cp16(&As[st * ASZ + m * AP + k4], Ap + (size_t)(m0 + m) * lda + kt + k4);
        }
    };
    auto loadB = [&](int kt, int st) {
        if (BT) {
            #pragma unroll
            for (int i = 0; i < 2; i++) {
                int idx = tid + i * 256;
                int n = idx >> 2, k4 = (idx & 3) << 2;
                cp16(&Bs[st * BSZ + n * AP + k4], Bp + (size_t)(n0 + n) * ldb + kt + k4);
            }
        } else if (BN == 128) {
            #pragma unroll
            for (int i = 0; i < 2; i++) {
                int idx = tid + i * 256;
                int k = idx >> 5, n4 = (idx & 31) << 2;
                cp16(&Bs[st * BSZ + k * BP + n4], Bp + (size_t)(kt + k) * ldb + n0 + n4);
            }
        } else {
            int k = tid >> 4, n4 = (tid & 15) << 2;
            cp16(&Bs[st * BSZ + k * BP + n4], Bp + (size_t)(kt + k) * ldb + n0 + n4);
        }
    };
    auto compute = [&](int st) {
        #pragma unroll
        for (int kk = 0; kk < 2; kk++) {
            const int kc = kk * 8 + t4;
            unsigned aF[4][4];
            #pragma unroll
            for (int i = 0; i < 4; i++) {
                int mb = wm * 64 + i * 16 + g;
                aF[i][0] = tf32u(As[st * ASZ + mb * AP + kc]);
                aF[i][1] = tf32u(As[st * ASZ + (mb + 8) * AP + kc]);
                aF[i][2] = tf32u(As[st * ASZ + mb * AP + kc + 4]);
                aF[i][3] = tf32u(As[st * ASZ + (mb + 8) * AP + kc + 4]);
            }
            unsigned bF[NT][2];
            #pragma unroll
            for (int j = 0; j < NT; j++) {
                int nb = wn * WN + j * 8 + g;
                if (BT) {
                    bF[j][0] = tf32u(Bs[st * BSZ + nb * AP + kc]);
                    bF[j][1] = tf32u(Bs[st * BSZ + nb * AP + kc + 4]);
                } else {
                    bF[j][0] = tf32u(Bs[st * BSZ + kc * BP + nb]);
                    bF[j][1] = tf32u(Bs[st * BSZ + (kc + 4) * BP + nb]);
                }
            }
            #pragma unroll
            for (int i = 0; i < 4; i++)
                #pragma unroll
                for (int j = 0; j < NT; j++)
                    mma_tf32(acc[i][j], aF[i], bF[j]);
        }
    };

    const int nt = K >> 4;
    loadA(0, 0); loadB(0, 0); cp_commit();
    for (int t = 0; t < nt; t++) {
        int cur = t & 1;
        if (t + 1 < nt) {
            loadA((t + 1) << 4, (t + 1) & 1);
            loadB((t + 1) << 4, (t + 1) & 1);
            cp_commit();
            cp_wait<1>();
        } else {
            cp_wait<0>();
        }
        __syncthreads();
        compute(cur);
        __syncthreads();
    }

    auto epi = [&](int row, int col, float2 v) {
        if (EPI == 4) {
            float2 old = *(const float2*)(Cp + (size_t)row * ldc + col);
            v.x = fmaf(v.x, alpha, old.x);
            v.y = fmaf(v.y, alpha, old.y);
            *(float2*)(Cp + (size_t)row * ldc + col) = v;
            return;
        }
        float2 bb = *(const float2*)(biasp + col);
        v.x += bb.x; v.y += bb.y;
        if (EPI == 1) { v.x = fmaxf(v.x, 0.f); v.y = fmaxf(v.y, 0.f); }
        if (EPI == 2) {
            float2 r = *(const float2*)(Rres + (size_t)row * ldc + col);
            v.x += r.x; v.y += r.y;
        }
        if (EPI == 3) {
            int h = col >> 6, d = col & 63;
            float* dst = Cp + ((((size_t)(row >> 10) * NH + h) * LL + (row & 1023)) * DKK + d);
            *(float2*)dst = v;
            return;
        }
        *(float2*)(Cp + (size_t)row * ldc + col) = v;
    };

    #pragma unroll
    for (int i = 0; i < 4; i++) {
        int r0 = m0 + wm * 64 + i * 16 + g;
        #pragma unroll
        for (int j = 0; j < NT; j++) {
            int col = n0 + wn * WN + j * 8 + t4 * 2;
            epi(r0,     col, make_float2(acc[i][j][0], acc[i][j][1]));
            epi(r0 + 8, col, make_float2(acc[i][j][2], acc[i][j][3]));
        }
    }
}

// ---------------- fused online-softmax + AV (flash consumer) ----------------
// Per CTA: q-block of 128 for one (b,h). Loop k in 32-wide tiles:
// read S tile, update running rowmax/rowsum, P=exp(S-m) in smem (tf32 at mma),
// rescale O accumulator, O += P @ V. Final: O/rowsum -> (b,l,h*64+d).
__global__ __launch_bounds__(256, 2) void softmax_av_kernel(
    const float* __restrict__ S, const float* __restrict__ V, float* __restrict__ O)
{
    constexpr int SP = 36;   // Ss row stride (32 + 4)
    constexpr int VP = 68;   // Vs row stride (64 + 4)
    __shared__ float Ss[128 * SP];
    __shared__ float Vs[32 * VP];
    __shared__ float rowScale[128];
    __shared__ float rowInv[128];

    const int tid = threadIdx.x;
    const int lane = tid & 31, w = tid >> 5;
    const int wm = w & 1, wn = w >> 1;
    const int g = lane >> 2, t4 = lane & 3;
    const int bh = blockIdx.z, b = bh / NH, h = bh % NH;
    const int q0 = blockIdx.y * 128;
    const float* Sp = S + ((size_t)bh * LL + q0) * LL;
    const float* Vp = V + (size_t)bh * LL * DKK;

    float acc[4][2][4];
    #pragma unroll
    for (int i = 0; i < 4; i++)
        #pragma unroll
        for (int j = 0; j < 2; j++)
            #pragma unroll
            for (int q = 0; q < 4; q++) acc[i][j][q] = 0.f;

    float rowM = -1e30f, rowL = 0.f;
    const int myrow = tid >> 1, half = tid & 1;

    float4 sv[4], vv[2];
    auto ldg = [&](int kt) {
        #pragma unroll
        for (int i = 0; i < 4; i++) {
            int idx = tid + i * 256;
            int q = idx >> 3, k4 = (idx & 7) << 2;
            sv[i] = *(const float4*)(Sp + (size_t)q * LL + kt + k4);
        }
        #pragma unroll
        for (int i = 0; i < 2; i++) {
            int idx = tid + i * 256;
            int k = idx >> 4, d4 = (idx & 15) << 2;
            vv[i] = *(const float4*)(Vp + (size_t)(kt + k) * DKK + d4);
        }
    };
    auto sts = [&]() {
        #pragma unroll
        for (int i = 0; i < 4; i++) {
            int idx = tid + i * 256;
            int q = idx >> 3, k4 = (idx & 7) << 2;
            *(float4*)(Ss + q * SP + k4) = sv[i];
        }
        #pragma unroll
        for (int i = 0; i < 2; i++) {
            int idx = tid + i * 256;
            int k = idx >> 4, d4 = (idx & 15) << 2;
            *(float4*)(Vs + k * VP + d4) = vv[i];
        }
    };

    ldg(0);
    for (int t = 0; t < 32; t++) {
        sts();
        __syncthreads();
        if (t + 1 < 32) ldg((t + 1) * 32);

        // ---- online-softmax stats: 2 threads per row, 16 cols each ----
        float* prow = Ss + myrow * SP + half * 16;
        float4 x0 = *(float4*)(prow +  0);
        float4 x1 = *(float4*)(prow +  4);
        float4 x2 = *(float4*)(prow +  8);
        float4 x3 = *(float4*)(prow + 12);
        float mx = fmaxf(fmaxf(fmaxf(x0.x, x0.y), fmaxf(x0.z, x0.w)),
                         fmaxf(fmaxf(x1.x, x1.y), fmaxf(x1.z, x1.w)));
        mx = fmaxf(mx, fmaxf(fmaxf(fmaxf(x2.x, x2.y), fmaxf(x2.z, x2.w)),
                             fmaxf(fmaxf(x3.x, x3.y), fmaxf(x3.z, x3.w))));
        mx = fmaxf(mx, __shfl_xor_sync(0xffffffffu, mx, 1));
        float mNew = fmaxf(rowM, mx);
        float scale = __expf(rowM - mNew);
        x0.x = __expf(x0.x - mNew); x0.y = __expf(x0.y - mNew);
        x0.z = __expf(x0.z - mNew); x0.w = __expf(x0.w - mNew);
        x1.x = __expf(x1.x - mNew); x1.y = __expf(x1.y - mNew);
        x1.z = __expf(x1.z - mNew); x1.w = __expf(x1.w - mNew);
        x2.x = __expf(x2.x - mNew); x2.y = __expf(x2.y - mNew);
        x2.z = __expf(x2.z - mNew); x2.w = __expf(x2.w - mNew);
        x3.x = __expf(x3.x - mNew); x3.y = __expf(x3.y - mNew);
        x3.z = __expf(x3.z - mNew); x3.w = __expf(x3.w - mNew);
        *(float4*)(prow +  0) = x0;
        *(float4*)(prow +  4) = x1;
        *(float4*)(prow +  8) = x2;
        *(float4*)(prow + 12) = x3;
        float sum = (x0.x + x0.y + x0.z + x0.w) + (x1.x + x1.y + x1.z + x1.w)
                  + (x2.x + x2.y + x2.z + x2.w) + (x3.x + x3.y + x3.z + x3.w);
        sum += __shfl_xor_sync(0xffffffffu, sum, 1);
        rowL = rowL * scale + sum;
        rowM = mNew;
        if (half == 0) rowScale[myrow] = scale;
        __syncthreads();

        // ---- rescale accumulator ----
        #pragma unroll
        for (int i = 0; i < 4; i++) {
            int r = wm * 64 + i * 16 + g;
            float s0 = rowScale[r], s1 = rowScale[r + 8];
            #pragma unroll
            for (int j = 0; j < 2; j++) {
                acc[i][j][0] *= s0; acc[i][j][1] *= s0;
                acc[i][j][2] *= s1; acc[i][j][3] *= s1;
            }
        }

        // ---- acc += P @ V ----
        #pragma unroll
        for (int kk = 0; kk < 4; kk++) {
            const int kc = kk * 8 + t4;
            unsigned aF[4][4];
            #pragma unroll
            for (int i = 0; i < 4; i++) {
                int mb = wm * 64 + i * 16 + g;
                aF[i][0] = tf32u(Ss[mb * SP + kc]);
                aF[i][1] = tf32u(Ss[(mb + 8) * SP + kc]);
                aF[i][2] = tf32u(Ss[mb * SP + kc + 4]);
                aF[i][3] = tf32u(Ss[(mb + 8) * SP + kc + 4]);
            }
            unsigned bF[2][2];
            #pragma unroll
            for (int j = 0; j < 2; j++) {
                int nb = wn * 16 + j * 8 + g;
                bF[j][0] = tf32u(Vs[kc * VP + nb]);
                bF[j][1] = tf32u(Vs[(kc + 4) * VP + nb]);
            }
            #pragma unroll
            for (int i = 0; i < 4; i++)
                #pragma unroll
                for (int j = 0; j < 2; j++)
                    mma_tf32(acc[i][j], aF[i], bF[j]);
        }
        __syncthreads();
    }

    if (half == 0) rowInv[myrow] = 1.f / rowL;
    __syncthreads();

    float* Op = O + ((size_t)b * LL + q0) * DM + h * DKK;
    #pragma unroll
    for (int i = 0; i < 4; i++) {
        int r0 = wm * 64 + i * 16 + g;
        float i0 = rowInv[r0], i1 = rowInv[r0 + 8];
        #pragma unroll
        for (int j = 0; j < 2; j++) {
            int col = wn * 16 + j * 8 + t4 * 2;
            *(float2*)(Op + (size_t)r0 * DM + col) =
                make_float2(acc[i][j][0] * i0, acc[i][j][1] * i0);
            *(float2*)(Op + (size_t)(r0 + 8) * DM + col) =
                make_float2(acc[i][j][2] * i1, acc[i][j][3] * i1);
        }
    }
}

// ---------------- relative-position bias MLP -> S (b,h,q,k) ----------------
__global__ __launch_bounds__(256) void posbias_kernel(
    const float* __restrict__ sx, const float* __restrict__ sy,
    const float* __restrict__ P1, const float* __restrict__ pb1,
    const float* __restrict__ P2, const float* __restrict__ pb2,
    float* __restrict__ S)
{
    __shared__ float sP1[2*PH], sPb1[PH], sP2[PH*NH], sPb2[NH];
    __shared__ float qx[16], qy[16], kx[16], ky[16];
    const int b  = blockIdx.z;
    const int q0 = blockIdx.y * 16, k0 = blockIdx.x * 16;
    const int tid = threadIdx.x;

    if (tid < 2*PH) sP1[tid] = P1[tid];
    if (tid < PH)   sPb1[tid] = pb1[tid];
    if (tid < NH)   sPb2[tid] = pb2[tid];
    for (int i = tid; i < PH*NH; i += 256) sP2[i] = P2[i];
    if (tid < 16) {
        qx[tid] = sx[b*LL + q0 + tid];
        qy[tid] = sy[b*LL + q0 + tid];
        kx[tid] = sx[b*LL + k0 + tid];
        ky[tid] = sy[b*LL + k0 + tid];
    }
    __syncthreads();

    const int kq = tid & 15;
    const int qq = tid >> 4;
    float rx = fminf(fmaxf(qx[qq] - kx[kq], -1000.f), 1000.f) * 0.001f;
    float ry = fminf(fmaxf(qy[qq] - ky[kq], -1000.f), 1000.f) * 0.001f;

    float hbuf[PH];
    #pragma unroll
    for (int j = 0; j < PH; j++)
        hbuf[j] = fmaxf(fmaf(rx, sP1[j], fmaf(ry, sP1[PH+j], sPb1[j])), 0.f);

    const int q = q0 + qq, k = k0 + kq;
    #pragma unroll
    for (int h = 0; h < NH; h++) {
        float s = sPb2[h];
        #pragma unroll
        for (int j = 0; j < PH; j++) s = fmaf(hbuf[j], sP2[j*NH + h], s);
        S[((size_t)(b*NH + h) * LL + q) * LL + k] = s;
    }
}

// ---------------- layernorm over last dim (768) ----------------
__global__ __launch_bounds__(256) void layernorm_kernel(
    const float* __restrict__ X, const float* __restrict__ g, const float* __restrict__ be,
    float* __restrict__ Y)
{
    __shared__ float red[256];
    const size_t row = blockIdx.x;
    const float* p = X + row * DM;
    float* o = Y + row * DM;
    const int tid = threadIdx.x;
    float v[3];
    float s = 0.f;
    #pragma unroll
    for (int i = 0; i < 3; i++) { v[i] = p[tid + i*256]; s += v[i]; }
    red[tid] = s; __syncthreads();
    for (int st = 128; st > 0; st >>= 1) { if (tid < st) red[tid] += red[tid+st]; __syncthreads(); }
    float mean = red[0] * (1.f/DM); __syncthreads();
    float sq = 0.f;
    #pragma unroll
    for (int i = 0; i < 3; i++) { float d = v[i] - mean; sq += d*d; }
    red[tid] = sq; __syncthreads();
    for (int st = 128; st > 0; st >>= 1) { if (tid < st) red[tid] += red[tid+st]; __syncthreads(); }
    float rstd = rsqrtf(red[0] * (1.f/DM) + 1e-5f);
    #pragma unroll
    for (int i = 0; i < 3; i++) {
        int c = tid + i*256;
        o[c] = (v[i] - mean) * rstd * g[c] + be[c];
    }
}

// ---------------- launch ----------------
extern "C" void kernel_launch(void* const* d_in, const int* in_sizes, int n_in,
                              void* d_out, int out_size)
{
    const float* src = (const float*)d_in[0];
    const float* sx  = (const float*)d_in[1];
    const float* sy  = (const float*)d_in[2];
    const float* Wq  = (const float*)d_in[3];  const float* bq  = (const float*)d_in[4];
    const float* Wk  = (const float*)d_in[5];  const float* bk  = (const float*)d_in[6];
    const float* Wv  = (const float*)d_in[7];  const float* bv  = (const float*)d_in[8];
    const float* Wo  = (const float*)d_in[9];  const float* bo  = (const float*)d_in[10];
    const float* P1  = (const float*)d_in[11]; const float* pb1 = (const float*)d_in[12];
    const float* P2  = (const float*)d_in[13]; const float* pb2 = (const float*)d_in[14];
    const float* W1  = (const float*)d_in[15]; const float* b1  = (const float*)d_in[16];
    const float* W2  = (const float*)d_in[17]; const float* b2  = (const float*)d_in[18];
    const float* g1  = (const float*)d_in[19]; const float* be1 = (const float*)d_in[20];
    const float* g2  = (const float*)d_in[21]; const float* be2 = (const float*)d_in[22];
    float* out = (float*)d_out;

    float *Q, *K, *V, *S, *O, *Xres, *X1, *H1;
    cudaGetSymbolAddress((void**)&Q,    g_Q);
    cudaGetSymbolAddress((void**)&K,    g_K);
    cudaGetSymbolAddress((void**)&V,    g_V);
    cudaGetSymbolAddress((void**)&S,    g_S);
    cudaGetSymbolAddress((void**)&O,    g_O);
    cudaGetSymbolAddress((void**)&Xres, g_Xres);
    cudaGetSymbolAddress((void**)&X1,   g_X1);
    cudaGetSymbolAddress((void**)&H1,   g_H1);

    // 1) relative-position bias -> S
    posbias_kernel<<<dim3(LL/16, LL/16, BB), 256>>>(sx, sy, P1, pb1, P2, pb2, S);

    // 2) fused QKV projections, scatter to (b,h,l,d)
    tgemm<3, false, 128, 32><<<dim3(18, ROWS/128, 1), 256>>>(
        src, DM, 0, Wq, DM, 0, bq, nullptr, Q, 0, 0, DM, 1.f,
        Wk, Wv, bk, bv, K, V);

    // 3) S = 0.125 * Q K^T + S(bias)
    tgemm<4, true, 128, 32><<<dim3(LL/128, LL/128, BB*NH), 256>>>(
        Q, DKK, (long)LL*DKK, K, DKK, (long)LL*DKK, nullptr, nullptr,
        S, LL, (long)LL*LL, DKK, 0.125f,
        nullptr, nullptr, nullptr, nullptr, nullptr, nullptr);

    // 4) fused softmax + (P @ V) -> O (b, l, h*64+d)
    softmax_av_kernel<<<dim3(1, LL/128, BB*NH), 256>>>(S, V, O);

    // 5) Xres = src + O @ Wo + bo ; LN1 -> X1
    tgemm<2, false, 64, 16><<<dim3(DM/64, ROWS/128, 1), 256>>>(
        O, DM, 0, Wo, DM, 0, bo, src, Xres, DM, 0, DM, 1.f,
        nullptr, nullptr, nullptr, nullptr, nullptr, nullptr);
    layernorm_kernel<<<ROWS, 256>>>(Xres, g1, be1, X1);

    // 6) FFN
    tgemm<1, false, 128, 32><<<dim3(FFD/128, ROWS/128, 1), 256>>>(
        X1, DM, 0, W1, FFD, 0, b1, nullptr, H1, FFD, 0, DM, 1.f,
        nullptr, nullptr, nullptr, nullptr, nullptr, nullptr);
    tgemm<2, false, 64, 16><<<dim3(DM/64, ROWS/128, 1), 256>>>(
        H1, FFD, 0, W2, DM, 0, b2, X1, Xres, DM, 0, FFD, 1.f,
        nullptr, nullptr, nullptr, nullptr, nullptr, nullptr);

    // 7) LN2 -> output
    layernorm_kernel<<<ROWS, 256>>>(Xres, g2, be2, out);
}